// round 10
// baseline (speedup 1.0000x reference)
#include <cuda_runtime.h>
#include <cuda_fp16.h>

#define IH 256
#define IW 256
#define NPIX (IH * IW)
#define NMAPS 88
#define SRC_ELEMS (NPIX * 3)

#define QSTRIDE 132
#define QROWS 129
#define COPYSZ (QROWS * QSTRIDE)    // 17028

#define NG8 (NMAPS * NPIX / 8)      // 720,896 threads (8 px each)
#define DTHREADS 256

// 2x2 fp16 quad, 32B: [0..3]=NW(r,g,b,0) [4..7]=NE [8..11]=SW [12..15]=SE.
// Copy (py,px): quad (ky,kx) covers rows (2ky-py, 2ky-py+1), cols (2kx-px, 2kx-px+1).
// OOB pixels stored zero -> bakes the reference's corner masks.
struct __align__(32) Quad { uint4 a, b; };
__device__ Quad g_quads[4 * COPYSZ];   // ~2.18 MB, L2-resident

__device__ __forceinline__ void px_fetch(const float* __restrict__ s, int r, int c, __half* out) {
    if ((unsigned)r < IH && (unsigned)c < IW) {
        const float* p = s + (r * IW + c) * 3;
        out[0] = __float2half(p[0]);
        out[1] = __float2half(p[1]);
        out[2] = __float2half(p[2]);
        out[3] = __float2half(0.f);
    } else {
        out[0] = out[1] = out[2] = out[3] = __float2half(0.f);
    }
}

__global__ void pack_src_kernel(const float* __restrict__ src) {
    int t0 = blockIdx.x * blockDim.x + threadIdx.x;
#pragma unroll
    for (int h = 0; h < 2; h++) {
        int t = t0 + h * (2 * COPYSZ);
        if (t >= 4 * COPYSZ) return;
        int c   = t / COPYSZ;
        int rem = t % COPYSZ;
        int ky = rem / QSTRIDE;
        int kx = rem % QSTRIDE;
        int py = c >> 1, px = c & 1;
        int r0 = 2 * ky - py;
        int c0 = 2 * kx - px;
        __align__(32) __half hh[16];
        px_fetch(src, r0,     c0,     hh + 0);
        px_fetch(src, r0,     c0 + 1, hh + 4);
        px_fetch(src, r0 + 1, c0,     hh + 8);
        px_fetch(src, r0 + 1, c0 + 1, hh + 12);
        g_quads[t] = *reinterpret_cast<Quad*>(hh);
    }
}

__device__ __forceinline__ float2 h2f(float v) {
    __half2 h = *reinterpret_cast<__half2*>(&v);
    return __half22float2(h);
}

// One thread = 8 consecutive pixels. 88*65536/8 = 720,896 threads (2816 x 256).
__global__ void __launch_bounds__(DTHREADS) deform_kernel(
    const float* __restrict__ motions, float* __restrict__ out) {
    int t = blockIdx.x * DTHREADS + threadIdx.x;

    // motions for 8 pixels: two 32B streaming loads
    const float* mbase = motions + (size_t)t * 16;
    float mv[16];
    asm("ld.global.cs.v8.f32 {%0,%1,%2,%3,%4,%5,%6,%7}, [%8];"
        : "=f"(mv[0]), "=f"(mv[1]), "=f"(mv[2]), "=f"(mv[3]),
          "=f"(mv[4]), "=f"(mv[5]), "=f"(mv[6]), "=f"(mv[7])
        : "l"(mbase));
    asm("ld.global.cs.v8.f32 {%0,%1,%2,%3,%4,%5,%6,%7}, [%8];"
        : "=f"(mv[8]),  "=f"(mv[9]),  "=f"(mv[10]), "=f"(mv[11]),
          "=f"(mv[12]), "=f"(mv[13]), "=f"(mv[14]), "=f"(mv[15])
        : "l"(mbase + 8));

    float fx[8], fy[8];
    const Quad* qp[8];
#pragma unroll
    for (int s = 0; s < 8; s++) {
        float x = fmaf(mv[s * 2 + 0], 128.f, 127.5f);   // [-0.5, 255.5)
        float y = fmaf(mv[s * 2 + 1], 128.f, 127.5f);
        int xw = __float2int_rd(x);   // [-1, 255]
        int yn = __float2int_rd(y);   // [-1, 255]
        fx[s] = x - (float)xw;
        fy[s] = y - (float)yn;
        int py = yn & 1, px = xw & 1;
        int ky = (yn + py) >> 1;      // [0,128]
        int kx = (xw + px) >> 1;      // [0,128]
        qp[s] = &g_quads[((py << 1) | px) * COPYSZ + ky * QSTRIDE + kx];
    }

    // 8 independent divergent 256-bit gathers, back-to-back (deep MLP).
    float q[8][8];
#pragma unroll
    for (int s = 0; s < 8; s++) {
        asm("ld.global.nc.v8.f32 {%0,%1,%2,%3,%4,%5,%6,%7}, [%8];"
            : "=f"(q[s][0]), "=f"(q[s][1]), "=f"(q[s][2]), "=f"(q[s][3]),
              "=f"(q[s][4]), "=f"(q[s][5]), "=f"(q[s][6]), "=f"(q[s][7])
            : "l"(qp[s]));
    }

    float r[24];
#pragma unroll
    for (int s = 0; s < 8; s++) {
        float wnw = (1.f - fy[s]) * (1.f - fx[s]);
        float wne = (1.f - fy[s]) * fx[s];
        float wsw = fy[s] * (1.f - fx[s]);
        float wse = fy[s] * fx[s];

        float2 nw = h2f(q[s][0]);
        float2 ne = h2f(q[s][2]);
        float2 sw = h2f(q[s][4]);
        float2 se = h2f(q[s][6]);
        float nwb = h2f(q[s][1]).x;
        float neb = h2f(q[s][3]).x;
        float swb = h2f(q[s][5]).x;
        float seb = h2f(q[s][7]).x;

        r[s * 3 + 0] = wnw * nw.x + wne * ne.x + wsw * sw.x + wse * se.x;
        r[s * 3 + 1] = wnw * nw.y + wne * ne.y + wsw * sw.y + wse * se.y;
        r[s * 3 + 2] = wnw * nwb  + wne * neb  + wsw * swb  + wse * seb;
    }

    // 24 floats = 96B contiguous, 32B-aligned: three 256-bit streaming stores.
    float* obase = out + (size_t)t * 24;
#pragma unroll
    for (int g = 0; g < 3; g++) {
        asm volatile("st.global.cs.v8.f32 [%0], {%1,%2,%3,%4,%5,%6,%7,%8};"
            :: "l"(obase + g * 8),
               "f"(r[g * 8 + 0]), "f"(r[g * 8 + 1]), "f"(r[g * 8 + 2]), "f"(r[g * 8 + 3]),
               "f"(r[g * 8 + 4]), "f"(r[g * 8 + 5]), "f"(r[g * 8 + 6]), "f"(r[g * 8 + 7])
            : "memory");
    }
}

extern "C" void kernel_launch(void* const* d_in, const int* in_sizes, int n_in,
                              void* d_out, int out_size) {
    const float* source  = (const float*)d_in[0];
    const float* motions = (const float*)d_in[1];
    if (n_in >= 2 && in_sizes[0] != SRC_ELEMS) {
        source  = (const float*)d_in[1];
        motions = (const float*)d_in[0];
    }

    pack_src_kernel<<<(2 * COPYSZ + 255) / 256, 256>>>(source);
    deform_kernel<<<NG8 / DTHREADS, DTHREADS>>>(motions, (float*)d_out);
}